// round 10
// baseline (speedup 1.0000x reference)
#include <cuda_runtime.h>
#include <cuda_bf16.h>
#include <cstdint>
#include <math.h>

typedef unsigned int       u32;
typedef unsigned long long u64;

// ---------------------------------------------------------------------------
// Scratch (static device globals - no allocations anywhere)
// ---------------------------------------------------------------------------
#define MAXACT (8*64*128*128)
__device__ float  g_bufA[MAXACT];
__device__ float  g_bufB[MAXACT];
__device__ float  g_part[4194304];
__device__ int4   g_tIdx[196416];
__device__ float4 g_tW  [196416];
__device__ float  g_vec[8*512];
__device__ float  g_fc1o[8*4096];
__device__ float  g_fc2o[8*4096];
__device__ __nv_bfloat16 g_Shi[75497472];
__device__ __nv_bfloat16 g_Slo[75497472];
__device__ __nv_bfloat16 g_Whi[14712832];
__device__ __nv_bfloat16 g_Wlo[14712832];

// ---------------------------------------------------------------------------
// Helpers
// ---------------------------------------------------------------------------
__device__ __forceinline__ void cp_async16(u32 dst, const void* src) {
    asm volatile("cp.async.cg.shared.global [%0], [%1], 16;" :: "r"(dst), "l"(src) : "memory");
}

__device__ __forceinline__ u32 smem_u32(const void* p) {
    u32 a;
    asm("{ .reg .u64 t; cvta.to.shared.u64 t, %1; cvt.u32.u64 %0, t; }" : "=r"(a) : "l"(p));
    return a;
}

// mma.sync m16n8k16 row.col f32.bf16.bf16.f32 (supported on plain sm_103)
__device__ __forceinline__ void mma16816(float* c, const u32* a, const u32* b) {
    asm volatile(
        "mma.sync.aligned.m16n8k16.row.col.f32.bf16.bf16.f32 "
        "{%0,%1,%2,%3}, {%4,%5,%6,%7}, {%8,%9}, {%0,%1,%2,%3};"
        : "+f"(c[0]), "+f"(c[1]), "+f"(c[2]), "+f"(c[3])
        : "r"(a[0]), "r"(a[1]), "r"(a[2]), "r"(a[3]), "r"(b[0]), "r"(b[1]));
}

__device__ __forceinline__ float* sel_buf(int s) {
    if (s == 1) return g_bufA;
    if (s == 2) return g_bufB;
    return g_part;
}

// ---------------------------------------------------------------------------
// Sampling-table kernel
// ---------------------------------------------------------------------------
__global__ void make_table_kernel(int H, int base)
{
    int p = blockIdx.x * blockDim.x + threadIdx.x;
    int HW = H * H;
    if (p >= HW) return;
    int y = p / H, x = p % H;
    float c = H * 0.5f - 0.5f;
    const float TWO_PI = 6.283185307179586f;
    const float PI4    = 0.7853981633974483f;
    float t = atan2f((float)x - c, (float)y - c);
    if (t < 0.f) t += TWO_PI;
    t = rintf(t * 10000.f) / 10000.f;

    #pragma unroll
    for (int k = 0; k < 9; k++) {
        float offy, offx;
        if (k == 4) { offy = 0.f; offx = 0.f; }
        else {
            int m = (k < 4) ? k : (k - 1);
            float ay = (float)(1 - k / 3);
            float ax = (float)(1 - k % 3);
            float ang = t + PI4 * (float)m;
            offy = cosf(ang) + ay;
            offx = sinf(ang) + ax;
        }
        float py = (float)(y - 1 + k / 3) + offy;
        float px = (float)(x - 1 + k % 3) + offx;
        float y0f = floorf(py), x0f = floorf(px);
        float wy = py - y0f, wx = px - x0f;
        int y0 = (int)y0f, x0 = (int)x0f;

        int4 ii; float4 ww;
        {
            int yy = y0, xx = x0;
            bool v = (yy >= 0 && yy <= H-1 && xx >= 0 && xx <= H-1);
            int yc = min(max(yy,0),H-1), xc = min(max(xx,0),H-1);
            ii.x = yc*H + xc; ww.x = v ? (1.f-wy)*(1.f-wx) : 0.f;
        }
        {
            int yy = y0, xx = x0+1;
            bool v = (yy >= 0 && yy <= H-1 && xx >= 0 && xx <= H-1);
            int yc = min(max(yy,0),H-1), xc = min(max(xx,0),H-1);
            ii.y = yc*H + xc; ww.y = v ? (1.f-wy)*wx : 0.f;
        }
        {
            int yy = y0+1, xx = x0;
            bool v = (yy >= 0 && yy <= H-1 && xx >= 0 && xx <= H-1);
            int yc = min(max(yy,0),H-1), xc = min(max(xx,0),H-1);
            ii.z = yc*H + xc; ww.z = v ? wy*(1.f-wx) : 0.f;
        }
        {
            int yy = y0+1, xx = x0+1;
            bool v = (yy >= 0 && yy <= H-1 && xx >= 0 && xx <= H-1);
            int yc = min(max(yy,0),H-1), xc = min(max(xx,0),H-1);
            ii.w = yc*H + xc; ww.w = v ? wy*wx : 0.f;
        }
        g_tIdx[base + k*HW + p] = ii;
        g_tW  [base + k*HW + p] = ww;
    }
}

// ---------------------------------------------------------------------------
// Weight prep: (O,C,3,3) fp32 -> [O][Kpad] bf16 hi/lo at offset woff
// ---------------------------------------------------------------------------
__global__ void wprep_kernel(const float* __restrict__ w, int woff,
                             int CK, int Kpad, int total)
{
    int i = blockIdx.x * blockDim.x + threadIdx.x;
    if (i >= total) return;
    int o = i / Kpad;
    int kk = i - o * Kpad;
    float v = 0.f;
    if (kk < CK) v = w[(size_t)o * CK + kk];
    __nv_bfloat16 h = __float2bfloat16(v);
    g_Whi[woff + i] = h;
    g_Wlo[woff + i] = __float2bfloat16(v - __bfloat162float(h));
}

// ---------------------------------------------------------------------------
// Sampler: bilinear im2col -> g_Shi/g_Slo [N][Kpad] bf16
// srcSel: 0 = external x pointer, 1 = g_bufA, 2 = g_bufB
// ---------------------------------------------------------------------------
__global__ void sample_kernel(const float* __restrict__ xext, int srcSel,
                              int tbase, int C, int HW, int Kpad, int total)
{
    int i = blockIdx.x * blockDim.x + threadIdx.x;
    if (i >= total) return;
    const float* x = xext;
    if (srcSel == 1) x = g_bufA;
    if (srcSel == 2) x = g_bufB;
    int c = i % C, n = i / C;
    int b = n / HW, p = n - b * HW;
    const float* xc = x + ((size_t)b * C + c) * HW;
    size_t ro = (size_t)n * Kpad + c * 9;
    #pragma unroll
    for (int k = 0; k < 9; k++) {
        int4   ii = __ldg(&g_tIdx[tbase + k*HW + p]);
        float4 ww = __ldg(&g_tW  [tbase + k*HW + p]);
        float s = ww.x*__ldg(xc+ii.x) + ww.y*__ldg(xc+ii.y)
                + ww.z*__ldg(xc+ii.z) + ww.w*__ldg(xc+ii.w);
        __nv_bfloat16 h = __float2bfloat16(s);
        g_Shi[ro + k] = h;
        g_Slo[ro + k] = __float2bfloat16(s - __bfloat162float(h));
    }
    if (c == C - 1) {
        __nv_bfloat16 z = __float2bfloat16(0.f);
        for (int kk = C*9; kk < Kpad; kk++) {
            g_Shi[(size_t)n*Kpad + kk] = z;
            g_Slo[(size_t)n*Kpad + kk] = z;
        }
    }
}

// ---------------------------------------------------------------------------
// mma.sync GEMM: D[n][o] = sum_k S[n][k]*W[o][k], bf16 hi/lo 3-pass split,
// fp32 register accumulators. CTA tile M=128 pixels x NT outputs, 256 threads
// (8 warps, warp tile 32 x NT/2). k-chunk 32 bf16, 2-stage cp.async pipeline.
// Smem rows padded to pitch 40 bf16 (80 B) -> conflict-free fragment LDS.
// outSel: 1 = g_bufA (+relu), 2 = g_bufB (+relu), 3 = g_part (no relu, slice kc)
// ---------------------------------------------------------------------------
template<int NT>
__global__ void __launch_bounds__(256, 1)
gemm_kernel(int woff, int outSel, int O, int Npix, int Kpad, int kSplit, int HW)
{
    extern __shared__ char sm[];
    const int tid  = threadIdx.x;
    const int wid  = tid >> 5;
    const int lane = tid & 31;
    const int g    = lane >> 2;     // fragment group row
    const int t    = lane & 3;      // fragment thread-in-group
    const int n0 = blockIdx.x * 128;
    const int o0 = blockIdx.y * NT;
    const int kc = blockIdx.z;
    const int nCh = (Kpad / kSplit) >> 5;     // chunks of k=32
    const int ci0 = kc * nCh;

    const int A_SZ = 128 * 80;                // one A buffer (hi or lo), bytes
    const int B_SZ = NT * 80;
    const int stageBytes = 2*A_SZ + 2*B_SZ;

    const int warpM = (wid & 3) * 32;
    const int warpN = (wid >> 2) * (NT/2);
    const int NTW = NT / 16;                  // 8-wide n-tiles per warp

    const u32 sb = smem_u32(sm);

    float acc[2][NTW][4];
    #pragma unroll
    for (int mt = 0; mt < 2; mt++)
        #pragma unroll
        for (int nt = 0; nt < NTW; nt++)
            #pragma unroll
            for (int r = 0; r < 4; r++) acc[mt][nt][r] = 0.f;

    // ---- chunk loader: [Ahi | Alo | Bhi | Blo], rows padded to 80 B ----
    // granules of 16 B: A rows 128 x 4, B rows NT x 4, each for hi and lo.
    const int nGran = 2*128*4 + 2*NT*4;

    for (int i = 0; i < nCh; i++) {
        int s = i & 1;
        // prefetch next chunk into other stage
        if (i + 1 < nCh) {
            int colOff = (ci0 + i + 1) * 32;
            u32 stBase = sb + (u32)((1 - s) * stageBytes);
            for (int gr = tid; gr < nGran; gr += 256) {
                if (gr < 512) {
                    int row = gr >> 2, gi = gr & 3;
                    cp_async16(stBase + (u32)(row*80 + gi*16),
                               g_Shi + (size_t)(n0+row)*Kpad + colOff + gi*8);
                } else if (gr < 1024) {
                    int gg = gr - 512;
                    int row = gg >> 2, gi = gg & 3;
                    cp_async16(stBase + (u32)(A_SZ + row*80 + gi*16),
                               g_Slo + (size_t)(n0+row)*Kpad + colOff + gi*8);
                } else if (gr < 1024 + NT*4) {
                    int gg = gr - 1024;
                    int row = gg >> 2, gi = gg & 3;
                    cp_async16(stBase + (u32)(2*A_SZ + row*80 + gi*16),
                               g_Whi + woff + (size_t)(o0+row)*Kpad + colOff + gi*8);
                } else {
                    int gg = gr - 1024 - NT*4;
                    int row = gg >> 2, gi = gg & 3;
                    cp_async16(stBase + (u32)(2*A_SZ + B_SZ + row*80 + gi*16),
                               g_Wlo + woff + (size_t)(o0+row)*Kpad + colOff + gi*8);
                }
            }
            asm volatile("cp.async.commit_group;" ::: "memory");
            asm volatile("cp.async.wait_group 1;" ::: "memory");
        } else if (i == 0) {
            // first iteration with no preload yet handled below
            asm volatile("cp.async.wait_group 0;" ::: "memory");
        } else {
            asm volatile("cp.async.wait_group 0;" ::: "memory");
        }
        // On the very first iteration stage 0 must be loaded synchronously:
        if (i == 0) {
            // issue loads for chunk 0 into stage 0 and wait for everything
            int colOff = ci0 * 32;
            u32 stBase = sb;
            for (int gr = tid; gr < nGran; gr += 256) {
                if (gr < 512) {
                    int row = gr >> 2, gi = gr & 3;
                    cp_async16(stBase + (u32)(row*80 + gi*16),
                               g_Shi + (size_t)(n0+row)*Kpad + colOff + gi*8);
                } else if (gr < 1024) {
                    int gg = gr - 512;
                    int row = gg >> 2, gi = gg & 3;
                    cp_async16(stBase + (u32)(A_SZ + row*80 + gi*16),
                               g_Slo + (size_t)(n0+row)*Kpad + colOff + gi*8);
                } else if (gr < 1024 + NT*4) {
                    int gg = gr - 1024;
                    int row = gg >> 2, gi = gg & 3;
                    cp_async16(stBase + (u32)(2*A_SZ + row*80 + gi*16),
                               g_Whi + woff + (size_t)(o0+row)*Kpad + colOff + gi*8);
                } else {
                    int gg = gr - 1024 - NT*4;
                    int row = gg >> 2, gi = gg & 3;
                    cp_async16(stBase + (u32)(2*A_SZ + B_SZ + row*80 + gi*16),
                               g_Wlo + woff + (size_t)(o0+row)*Kpad + colOff + gi*8);
                }
            }
            asm volatile("cp.async.commit_group;" ::: "memory");
            asm volatile("cp.async.wait_group 0;" ::: "memory");
        }
        __syncthreads();

        // ---- compute chunk from stage s ----
        const char* stageP = sm + s * stageBytes;
        const char* Ah = stageP;
        const char* Al = stageP + A_SZ;
        const char* Bh = stageP + 2*A_SZ;
        const char* Bl = stageP + 2*A_SZ + B_SZ;

        #pragma unroll
        for (int k0 = 0; k0 < 32; k0 += 16) {
            u32 ah[2][4], al[2][4];
            #pragma unroll
            for (int mt = 0; mt < 2; mt++) {
                int r0 = warpM + mt*16 + g;
                int cA = (k0 + 2*t) * 2;
                ah[mt][0] = *(const u32*)(Ah + r0*80 + cA);
                ah[mt][1] = *(const u32*)(Ah + (r0+8)*80 + cA);
                ah[mt][2] = *(const u32*)(Ah + r0*80 + cA + 16);
                ah[mt][3] = *(const u32*)(Ah + (r0+8)*80 + cA + 16);
                al[mt][0] = *(const u32*)(Al + r0*80 + cA);
                al[mt][1] = *(const u32*)(Al + (r0+8)*80 + cA);
                al[mt][2] = *(const u32*)(Al + r0*80 + cA + 16);
                al[mt][3] = *(const u32*)(Al + (r0+8)*80 + cA + 16);
            }
            u32 bh[NTW][2], bl[NTW][2];
            #pragma unroll
            for (int nt = 0; nt < NTW; nt++) {
                int rn = warpN + nt*8 + g;
                int cB = (k0 + 2*t) * 2;
                bh[nt][0] = *(const u32*)(Bh + rn*80 + cB);
                bh[nt][1] = *(const u32*)(Bh + rn*80 + cB + 16);
                bl[nt][0] = *(const u32*)(Bl + rn*80 + cB);
                bl[nt][1] = *(const u32*)(Bl + rn*80 + cB + 16);
            }
            #pragma unroll
            for (int mt = 0; mt < 2; mt++) {
                #pragma unroll
                for (int nt = 0; nt < NTW; nt++) {
                    mma16816(acc[mt][nt], ah[mt], bh[nt]);
                    mma16816(acc[mt][nt], ah[mt], bl[nt]);
                    mma16816(acc[mt][nt], al[mt], bh[nt]);
                }
            }
        }
        __syncthreads();
    }

    // ---- epilogue: direct register stores (+relu / split-K slice) ----
    float* ob = sel_buf(outSel);
    int doRelu = 1;
    if (outSel == 3) {
        ob = g_part + (size_t)kc * (size_t)O * (size_t)Npix;
        doRelu = 0;
    }
    #pragma unroll
    for (int mt = 0; mt < 2; mt++) {
        #pragma unroll
        for (int nt = 0; nt < NTW; nt++) {
            int pr0 = n0 + warpM + mt*16 + g;
            int pr1 = pr0 + 8;
            int oc  = o0 + warpN + nt*8 + 2*t;
            int b0 = pr0 / HW, p0 = pr0 - b0 * HW;
            int b1 = pr1 / HW, p1 = pr1 - b1 * HW;
            float v0 = acc[mt][nt][0];
            float v1 = acc[mt][nt][1];
            float v2 = acc[mt][nt][2];
            float v3 = acc[mt][nt][3];
            if (doRelu) {
                v0 = fmaxf(v0, 0.f); v1 = fmaxf(v1, 0.f);
                v2 = fmaxf(v2, 0.f); v3 = fmaxf(v3, 0.f);
            }
            ob[((size_t)b0 * O + oc)     * (size_t)HW + p0] = v0;
            ob[((size_t)b0 * O + oc + 1) * (size_t)HW + p0] = v1;
            ob[((size_t)b1 * O + oc)     * (size_t)HW + p1] = v2;
            ob[((size_t)b1 * O + oc + 1) * (size_t)HW + p1] = v3;
        }
    }
}

// ---------------------------------------------------------------------------
// Split-K reduce + ReLU (deterministic)
// ---------------------------------------------------------------------------
__global__ void reduce_relu_kernel(int outSel, int n, int kSplit)
{
    int i = blockIdx.x * blockDim.x + threadIdx.x;
    if (i >= n) return;
    float s = 0.f;
    for (int j = 0; j < kSplit; j++) s += g_part[(size_t)j*n + i];
    float* out = sel_buf(outSel);
    out[i] = fmaxf(s, 0.f);
}

// ---------------------------------------------------------------------------
// 2x2 max pool: inSel -> outSel
// ---------------------------------------------------------------------------
__global__ void pool_kernel(int inSel, int outSel, int C, int H)
{
    const float* in = sel_buf(inSel);
    float* out = sel_buf(outSel);
    int Ho = H / 2;
    int total = 8 * C * Ho * Ho;
    int i = blockIdx.x * blockDim.x + threadIdx.x;
    if (i >= total) return;
    int xo = i % Ho; int t = i / Ho;
    int yo = t % Ho; t /= Ho;
    int cc = t % C;  int b = t / C;
    const float* base = in + (((size_t)b*C + cc)*H + yo*2)*H + xo*2;
    out[i] = fmaxf(fmaxf(base[0], base[1]), fmaxf(base[H], base[H+1]));
}

// (8,512,4,4) in g_bufB -> (8,512) mean in g_vec
__global__ void avg_kernel()
{
    int i = blockIdx.x * blockDim.x + threadIdx.x;
    if (i >= 8*512) return;
    const float* p = g_bufB + (size_t)i * 16;
    float s = 0.f;
    #pragma unroll
    for (int j = 0; j < 16; j++) s += p[j];
    g_vec[i] = s * (1.f/16.f);
}

// ---------------------------------------------------------------------------
// FC layers
// ---------------------------------------------------------------------------
__global__ void fc_kernel(const float* __restrict__ W, const float* __restrict__ bias,
                          float* dout, int stage, int K, int O)
{
    const float* x = g_vec;
    if (stage == 1) x = g_fc1o;
    if (stage == 2) x = g_fc2o;
    float* y = g_fc1o;
    if (stage == 1) y = g_fc2o;
    if (stage == 2) y = dout;
    int relu = (stage < 2) ? 1 : 0;

    int o = blockIdx.x;
    float acc[8];
    #pragma unroll
    for (int i = 0; i < 8; i++) acc[i] = 0.f;
    const float* wr = W + (size_t)o * K;
    for (int k = threadIdx.x; k < K; k += 128) {
        float wv = wr[k];
        #pragma unroll
        for (int b = 0; b < 8; b++) acc[b] = fmaf(x[(size_t)b*K + k], wv, acc[b]);
    }
    __shared__ float red[8][128];
    #pragma unroll
    for (int b = 0; b < 8; b++) red[b][threadIdx.x] = acc[b];
    __syncthreads();
    for (int s = 64; s > 0; s >>= 1) {
        if (threadIdx.x < s) {
            #pragma unroll
            for (int b = 0; b < 8; b++)
                red[b][threadIdx.x] += red[b][threadIdx.x + s];
        }
        __syncthreads();
    }
    if (threadIdx.x < 8) {
        int b = threadIdx.x;
        float v = red[b][0] + bias[o];
        if (relu) v = fmaxf(v, 0.f);
        y[(size_t)b*O + o] = v;
    }
}

// ---------------------------------------------------------------------------
// Host orchestration
// ---------------------------------------------------------------------------
extern "C" void kernel_launch(void* const* d_in, const int* in_sizes, int n_in,
                              void* d_out, int out_size)
{
    const float* x = (const float*)d_in[0];
    const float* w[13];
    for (int i = 0; i < 13; i++) w[i] = (const float*)d_in[1+i];
    const float* fc1w = (const float*)d_in[14];
    const float* fc1b = (const float*)d_in[15];
    const float* fc2w = (const float*)d_in[16];
    const float* fc2b = (const float*)d_in[17];
    const float* fc3w = (const float*)d_in[18];
    const float* fc3b = (const float*)d_in[19];

    // dynamic smem: NT=64 -> 2*(2*10240+2*5120)=61440; NT=128 -> 81920
    cudaFuncSetAttribute(gemm_kernel<64>,
                         cudaFuncAttributeMaxDynamicSharedMemorySize, 61440);
    cudaFuncSetAttribute(gemm_kernel<128>,
                         cudaFuncAttributeMaxDynamicSharedMemorySize, 81920);

    // sampling tables
    const int resz[5]  = {128, 64, 32, 16, 8};
    const int tbase[5] = {0, 147456, 184320, 193536, 195840};
    for (int i = 0; i < 5; i++) {
        int hw = resz[i]*resz[i];
        make_table_kernel<<<(hw + 255)/256, 256>>>(resz[i], tbase[i]);
    }

    // weight prep
    const int lC[13] = {3,64,64,128,128,256,256,256,512,512,512,512,512};
    const int lO[13] = {64,64,128,128,256,256,256,512,512,512,512,512,512};
    int kpad[13];
    int woff[13];
    int wacc = 0;
    for (int i = 0; i < 13; i++) {
        int ck = lC[i] * 9;
        kpad[i] = ((ck + 63) / 64) * 64;
        woff[i] = wacc;
        int total = lO[i] * kpad[i];
        wprep_kernel<<<(total + 255)/256, 256>>>(w[i], woff[i], ck, kpad[i], total);
        wacc += total;
    }

    // per-layer schedule
    const int lH[13]   = {128,128,64,64,32,32,32,16,16,16,8,8,8};
    const int lKS[13]  = {1,1,1,1,1,1,1,2,2,2,8,8,8};
    const int srcSel[13] = {0,1,1,2,2,1,2,2,1,2,2,1,2};
    const int dstSel[13] = {1,2,2,1,1,2,1,1,2,1,1,2,1};

    for (int li = 0; li < 13; li++) {
        int C = lC[li], O = lO[li], H = lH[li], kSplit = lKS[li];
        int HW = H * H;
        int Kpad = kpad[li];
        int ti = 4;
        if (HW == 16384) ti = 0;
        else if (HW == 4096) ti = 1;
        else if (HW == 1024) ti = 2;
        else if (HW == 256) ti = 3;

        int total = 8 * HW * C;
        sample_kernel<<<(total + 255)/256, 256>>>(x, srcSel[li], tbase[ti],
                                                  C, HW, Kpad, total);

        int Npix = 8 * HW;
        int NT = 64;
        if (O >= 128) NT = 128;
        dim3 grid(Npix/128, O/NT, kSplit);
        int outSel = dstSel[li];
        if (kSplit > 1) outSel = 3;
        if (NT == 64) {
            gemm_kernel<64><<<grid, 256, 61440>>>(woff[li], outSel,
                                                  O, Npix, Kpad, kSplit, HW);
        } else {
            gemm_kernel<128><<<grid, 256, 81920>>>(woff[li], outSel,
                                                   O, Npix, Kpad, kSplit, HW);
        }
        if (kSplit > 1) {
            int n = O * Npix;
            reduce_relu_kernel<<<(n + 255)/256, 256>>>(dstSel[li], n, kSplit);
        }

        if (li == 1)  pool_kernel<<<(8*64*64*64  + 255)/256, 256>>>(2, 1, 64, 128);
        if (li == 3)  pool_kernel<<<(8*128*32*32 + 255)/256, 256>>>(1, 2, 128, 64);
        if (li == 6)  pool_kernel<<<(8*256*16*16 + 255)/256, 256>>>(1, 2, 256, 32);
        if (li == 9)  pool_kernel<<<(8*512*8*8   + 255)/256, 256>>>(1, 2, 512, 16);
        if (li == 12) pool_kernel<<<(8*512*4*4   + 255)/256, 256>>>(1, 2, 512, 8);
    }

    avg_kernel<<<(8*512 + 255)/256, 256>>>();

    fc_kernel<<<4096, 128>>>(fc1w, fc1b, (float*)d_out, 0, 512, 4096);
    fc_kernel<<<4096, 128>>>(fc2w, fc2b, (float*)d_out, 1, 4096, 4096);
    fc_kernel<<<30,   128>>>(fc3w, fc3b, (float*)d_out, 2, 4096, 30);
}